// round 17
// baseline (speedup 1.0000x reference)
#include <cuda_runtime.h>
#include <math.h>

#define BB 64
#define DD 512
#define HH 8
#define EPSF 1e-8f
#define NTHR 256          // 8 warps; warp = head, lanes = 32 sorted positions
#define ITILE 32
#define NTILES (DD / ITILE)   // 16
#define CAPW 32           // sparse window cap
#define DENSE_T 12        // >= this many dense lanes -> lockstep packed path

typedef unsigned long long ull;

__device__ float g_sv[BB * DD];   // sorted x values per batch row
__device__ int   g_si[BB * DD];   // original indices (permutation)

__device__ __forceinline__ ull pk2(float lo, float hi) {
    ull r; asm("mov.b64 %0, {%1, %2};" : "=l"(r) : "f"(lo), "f"(hi)); return r;
}
__device__ __forceinline__ void upk2(ull v, float& lo, float& hi) {
    asm("mov.b64 {%0, %1}, %2;" : "=f"(lo), "=f"(hi) : "l"(v));
}
__device__ __forceinline__ ull fma2(ull a, ull b, ull c) {
    ull r; asm("fma.rn.f32x2 %0, %1, %2, %3;" : "=l"(r) : "l"(a), "l"(b), "l"(c)); return r;
}
__device__ __forceinline__ ull add2(ull a, ull b) {
    ull r; asm("add.rn.f32x2 %0, %1, %2;" : "=l"(r) : "l"(a), "l"(b)); return r;
}
__device__ __forceinline__ float frcp(float v) {
    float r; asm("rcp.approx.f32 %0, %1;" : "=f"(r) : "f"(v)); return r;
}
__device__ __forceinline__ float fex2(float v) {
    float r; asm("ex2.approx.f32 %0, %1;" : "=f"(r) : "f"(v)); return r;
}
__device__ __forceinline__ int redux_max_u32(int v) {
    int r; asm("redux.sync.max.u32 %0, %1, 0xffffffff;" : "=r"(r) : "r"(v)); return r;
}

// ---------- Kernel 1: bitonic sort of each batch row (value, index) ----------
// Sync-strength optimization: for stride j <= 16, compare-swap pairs are
// confined to one warp's 32-element segment (tid and tid^j share a warp, in
// both the base=0 and base=256 halves), so __syncwarp() suffices. Block-wide
// __syncthreads() only when the current substage wrote cross-warp (j >= 32)
// or the NEXT substage reads cross-warp (j==1 with next stride k >= 32).
__global__ __launch_bounds__(256)
void sort_kernel(const float* __restrict__ x)
{
    __shared__ float vals[DD];
    __shared__ int   idxs[DD];
    const int b   = blockIdx.x;
    const int tid = threadIdx.x;

    vals[tid]       = x[b * DD + tid];
    vals[tid + 256] = x[b * DD + tid + 256];
    idxs[tid]       = tid;
    idxs[tid + 256] = tid + 256;
    __syncthreads();

    for (int k = 2; k <= DD; k <<= 1) {
        for (int j = k >> 1; j > 0; j >>= 1) {
            #pragma unroll
            for (int base = 0; base < DD; base += 256) {
                int i = base + tid;
                int p = i ^ j;
                if (p > i) {
                    bool up = ((i & k) == 0);
                    float a = vals[i], c = vals[p];
                    if ((a > c) == up) {
                        vals[i] = c; vals[p] = a;
                        int t = idxs[i]; idxs[i] = idxs[p]; idxs[p] = t;
                    }
                }
            }
            if (j >= 32 || (j == 1 && k >= 32)) __syncthreads();
            else                                __syncwarp();
        }
    }

    g_sv[b * DD + tid]       = vals[tid];
    g_sv[b * DD + tid + 256] = vals[tid + 256];
    g_si[b * DD + tid]       = idxs[tid];
    g_si[b * DD + tid + 256] = idxs[tid + 256];
}

// ---------- Kernel 2: windowed softmax attention over sorted values ----------
__global__ __launch_bounds__(NTHR)
void flattn_kernel(const float* __restrict__ alphas,
                   const float* __restrict__ betas,
                   float* __restrict__ out)
{
    __shared__ __align__(16) float sv[DD];
    __shared__ float partial[NTHR];   // [h][lane]

    const int b    = blockIdx.y;
    const int tile = blockIdx.x;      // 0..15, block of 32 sorted positions
    const int tid  = threadIdx.x;
    const int h    = tid >> 5;        // warp = head (aqs warp-uniform!)
    const int lane = tid & 31;
    const int pos  = tile * ITILE + lane;

    const float4* svg = (const float4*)(g_sv + b * DD);
    float4* svw = (float4*)sv;
    #pragma unroll
    for (int k = tid; k < DD / 4; k += NTHR) svw[k] = svg[k];
    __syncthreads();

    const float aq = alphas[h * 3 + 0];
    const float ak = alphas[h * 3 + 1];
    const float av = alphas[h * 3 + 2];
    const float bq = betas[h * 3 + 0];
    const float bk = betas[h * 3 + 1];

    const float inv_sqrt_d = 0.044194173824159216f;  // 1/sqrt(512)
    const float INV_L2E    = 0.6931471805599453f;    // ln(2)

    const float xi  = sv[pos];
    const float c   = bq - fmaf(ak, xi, bk);   // q_j - k_i = aq*x_j + c
    const float aqs = aq * INV_L2E;            // warp-uniform
    const float cs  = c  * INV_L2E;            // per-lane
    const float EPS_S = EPSF * INV_L2E;

    const float root = -cs * frcp(aqs);

    // Search 1: idx = #elements < root (9 steps + saturation fixup).
    int idx = 0;
    #pragma unroll
    for (int s = 256; s > 0; s >>= 1) {
        if (sv[idx + s - 1] < root) idx += s;
    }
    if (sv[idx] < root) idx++;

    float tmin = 3.0e38f;
    #pragma unroll
    for (int o = -2; o <= 2; o++) {
        int k = idx + o;
        if (k >= 0 && k < DD)
            tmin = fminf(tmin, fabsf(fmaf(aqs, sv[k], cs)));
    }
    tmin = fmaxf(tmin, EPS_S);
    float mL2E = frcp(tmin);
    const float negm = -mL2E;

    // Window: weight >= ~2^-40  <=>  x in [root-hw, root+hw].
    float th = (mL2E > 41.0f) ? frcp(mL2E - 40.0f) * 1.00002f : 3.0e38f;
    float hw = th * frcp(fabsf(aqs));
    hw = fmaf(fabsf(root), 1e-6f, hw * 1.0001f + 1e-6f);
    const float xlo = root - hw;
    const float xhi = root + hw;

    // Searches 2+3 interleaved, with saturation fixups ([0, 512] range).
    int lo = 0, hi = 0;
    #pragma unroll
    for (int s = 256; s > 0; s >>= 1) {
        if (sv[lo + s - 1] <  xlo) lo += s;
        if (sv[hi + s - 1] <= xhi) hi += s;
    }
    if (sv[lo] <  xlo) lo++;
    if (sv[hi] <= xhi) hi++;

    int nw = hi - lo;
    bool dense = (nw > CAPW) || (nw < 1);
    if (nw < 1) { lo = 0; hi = DD; }          // safety: full range in coop path

    const unsigned FULL = 0xffffffffu;
    unsigned dmask = __ballot_sync(FULL, dense);
    int nd = __popc(dmask);

    float wsum = 0.0f, wx = 0.0f;

    // ---- Tier 1: sparse lanes, lockstep counted loop to warp-max nw ----
    int nws = dense ? 0 : nw;
    int nwmax = redux_max_u32(nws);
    for (int t = 0; t < nwmax; t++) {
        int k = lo + t;
        if (!dense && k < hi) {
            float xv = sv[k];
            float tt = fmaxf(fabsf(fmaf(aqs, xv, cs)), EPS_S);
            float e  = fex2(frcp(tt) + negm);
            wsum += e;
            wx = fmaf(e, xv, wx);
        }
    }

    if (nd >= DENSE_T) {
        // ---- Tier 3: many dense lanes -> packed full loop (per-lane) ----
        if (dense) {
            const ull aq2 = pk2(aqs, aqs);
            const ull c2  = pk2(cs, cs);
            const ulonglong2* sv2 = (const ulonglong2*)sv;
            ull w2 = 0ULL, w2b = 0ULL, wx2 = 0ULL, wx2b = 0ULL;
            #pragma unroll 4
            for (int jq = 0; jq < DD / 4; jq++) {
                ulonglong2 xq = sv2[jq];
                ull x01 = xq.x, x23 = xq.y;

                ull d01 = fma2(aq2, x01, c2);
                ull d23 = fma2(aq2, x23, c2);
                float da, db, dc, dd;
                upk2(d01, da, db);
                upk2(d23, dc, dd);

                float ta = fmaxf(fabsf(da), EPS_S);
                float tb = fmaxf(fabsf(db), EPS_S);
                float tc = fmaxf(fabsf(dc), EPS_S);
                float td = fmaxf(fabsf(dd), EPS_S);

                float ea = fex2(frcp(ta) + negm);
                float eb = fex2(frcp(tb) + negm);
                float ec = fex2(frcp(tc) + negm);
                float ed = fex2(frcp(td) + negm);

                ull e01 = pk2(ea, eb);
                ull e23 = pk2(ec, ed);
                w2   = add2(w2,  e01);
                w2b  = add2(w2b, e23);
                wx2  = fma2(e01, x01, wx2);
                wx2b = fma2(e23, x23, wx2b);
            }
            float wl, wh2, wbl, wbh, wxl, wxh, wxbl, wxbh;
            upk2(w2, wl, wh2);
            upk2(w2b, wbl, wbh);
            upk2(wx2, wxl, wxh);
            upk2(wx2b, wxbl, wxbh);
            wsum = (wl + wh2) + (wbl + wbh);
            wx   = (wxl + wxh) + (wxbl + wxbh);
        }
    } else {
        // ---- Tier 2: few dense rows -> warp-cooperative, one row at a time ----
        while (dmask) {
            int r = __ffs(dmask) - 1;
            dmask &= dmask - 1;
            int   lor   = __shfl_sync(FULL, lo,   r);
            int   hir   = __shfl_sync(FULL, hi,   r);
            float csr   = __shfl_sync(FULL, cs,   r);
            float negmr = __shfl_sync(FULL, negm, r);

            float ws = 0.0f, wxr = 0.0f;
            for (int k = lor + lane; k < hir; k += 32) {
                float xv = sv[k];
                float tt = fmaxf(fabsf(fmaf(aqs, xv, csr)), EPS_S);
                float e  = fex2(frcp(tt) + negmr);
                ws += e;
                wxr = fmaf(e, xv, wxr);
            }
            #pragma unroll
            for (int o = 16; o > 0; o >>= 1) {
                ws  += __shfl_xor_sync(FULL, ws,  o);
                wxr += __shfl_xor_sync(FULL, wxr, o);
            }
            if (lane == r) { wsum = ws; wx = wxr; }
        }
    }

    partial[tid] = av * inv_sqrt_d * (wx * frcp(wsum));
    __syncthreads();

    // ---- Cross-head sum; store to ORIGINAL index (permutation scatter) ----
    if (tid < ITILE) {
        float bconst = 0.0f;
        #pragma unroll
        for (int hh = 0; hh < HH; hh++) bconst += betas[hh * 3 + 2];

        float s = 0.0f;
        #pragma unroll
        for (int hh = 0; hh < HH; hh++) s += partial[hh * ITILE + tid];

        int p  = tile * ITILE + tid;
        int oi = g_si[b * DD + p];
        out[b * DD + oi] = sv[p] + s + bconst * inv_sqrt_d;
    }
}

extern "C" void kernel_launch(void* const* d_in, const int* in_sizes, int n_in,
                              void* d_out, int out_size)
{
    const float* x      = (const float*)d_in[0];
    const float* alphas = (const float*)d_in[1];
    const float* betas  = (const float*)d_in[2];
    float* out = (float*)d_out;

    sort_kernel<<<BB, 256>>>(x);
    dim3 grid(NTILES, BB);   // (16, 64) = 1024 CTAs
    flattn_kernel<<<grid, NTHR>>>(alphas, betas, out);
}